// round 7
// baseline (speedup 1.0000x reference)
#include <cuda_runtime.h>

typedef unsigned long long u64;

#define CC      32
#define TT      256
#define HALO    63
#define NTHR    320
#define LLEN    90000
#define NTILES  352
#define NB      8
#define DOWNL   22500
#define FLATN   (64*DOWNL)
#define SLICE   3200
#define NSLICE  450

#define STR     328
#define OFF_HS  64
#define OFF_OUT (OFF_HS + 32*STR)     // 10560
#define OFF_B   (OFF_OUT + 32*STR)    // 21056
#define OFF_XS  (OFF_B + 768)         // 21824
#define SMF     (OFF_XS + 324)        // 22148 floats ~88.6KB

__device__ float g_y[NB * FLATN];
__device__ float g_partial[NSLICE * 64 * NB];
// packed dup'd weights (filled by k_prep each launch)
__device__ float4 g_wFG[6*32*4*2*8];  // [blk][c][i][f/g][og] = (w0,w0,w1,w1)
__device__ float4 g_wSR[6*32*4*8];    // [blk][o][part][og]  = (wA,wA,wB,wB)

// ---- f32x2 helpers ----
__device__ __forceinline__ u64 f2fma(u64 a, u64 b, u64 c) {
    u64 d; asm("fma.rn.f32x2 %0, %1, %2, %3;" : "=l"(d) : "l"(a), "l"(b), "l"(c)); return d;
}
__device__ __forceinline__ u64 f2add(u64 a, u64 b) {
    u64 d; asm("add.rn.f32x2 %0, %1, %2;" : "=l"(d) : "l"(a), "l"(b)); return d;
}
__device__ __forceinline__ u64 dup2(float x) {
    u64 d; unsigned r = __float_as_uint(x);
    asm("mov.b64 %0, {%1, %1};" : "=l"(d) : "r"(r)); return d;
}
__device__ __forceinline__ u64 pack2(float lo, float hi) {
    u64 d;
    asm("mov.b64 %0, {%1, %2};" : "=l"(d)
        : "r"(__float_as_uint(lo)), "r"(__float_as_uint(hi)));
    return d;
}
__device__ __forceinline__ float2 unp(u64 a) {
    unsigned x, y; asm("mov.b64 {%0, %1}, %2;" : "=r"(x), "=r"(y) : "l"(a));
    return make_float2(__uint_as_float(x), __uint_as_float(y));
}
// tanh(f)*sigmoid(g) with one reciprocal: 3 MUFU total
__device__ __forceinline__ float gact(float f, float g) {
    float e = __expf(-2.f * fabsf(f));
    float q = __expf(-g);
    float v = __fdividef(1.f - e, (1.f + e) * (1.f + q));
    return copysignf(v, f);
}

// ---------------------------------------------------------------------------
// Prep: pack weights into duplicated f32x2-ready layouts (global, L1-hot).
// ---------------------------------------------------------------------------
__global__ void k_prep(const float* __restrict__ Wf, const float* __restrict__ Wg,
                       const float* __restrict__ Ws, const float* __restrict__ Wr)
{
    int idx = blockIdx.x * 256 + threadIdx.x;
    if (idx < 12288) {   // fg: [blk][c][i][k][og]
        int og = idx & 7, k = (idx >> 3) & 1, i = (idx >> 4) & 3;
        int c = (idx >> 6) & 31, blk = idx >> 11;
        int o = og * 4 + i;
        const float* W = k ? Wg : Wf;
        float w0 = W[((size_t)(blk*32 + o)*32 + c)*2 + 0];
        float w1 = W[((size_t)(blk*32 + o)*32 + c)*2 + 1];
        g_wFG[idx] = make_float4(w0, w0, w1, w1);
    }
    if (idx < 6144) {    // sr: [blk][o][part][og], part: 0=Ws i01,1=Ws i23,2=Wr i01,3=Wr i23
        int og = idx & 7, part = (idx >> 3) & 3, o = (idx >> 5) & 31, blk = idx >> 10;
        const float* W = (part & 2) ? Wr : Ws;
        int p2 = (part & 1) * 2;
        float a = W[blk*1024 + (og*4 + p2    )*32 + o];
        float b = W[blk*1024 + (og*4 + p2 + 1)*32 + o];
        g_wSR[idx] = make_float4(a, a, b, b);
    }
}

// ---------------------------------------------------------------------------
// Phase A: gated conv, 4 outputs (o=og*4+i) x 4 position-pairs (base+2jp).
// Weights via coalesced LDG (dedup'd), h pairs via direct LDS.64.
// ---------------------------------------------------------------------------
template<int D>
__device__ __forceinline__ void phaseA(float* sm, const ulonglong2* __restrict__ wblk,
                                       const float* __restrict__ bb, int og, int base)
{
    u64 af[4][4], ag[4][4];
    #pragma unroll
    for (int i = 0; i < 4; i++) {
        u64 bfv = dup2(bb[2*(og*4 + i)]);
        u64 bgv = dup2(bb[2*(og*4 + i) + 1]);
        #pragma unroll
        for (int jp = 0; jp < 4; jp++) { af[i][jp] = bfv; ag[i][jp] = bgv; }
    }
    const float* hb = sm + OFF_HS + base;

    #pragma unroll 2
    for (int c = 0; c < 32; c++) {
        const float* hr = hb + c*STR;
        u64 hcp[4], hpp[4];
        if (D == 1) {
            float4 vm = *(const float4*)(hr - 4);
            float4 h0 = *(const float4*)(hr);
            float4 h1 = *(const float4*)(hr + 4);
            hcp[0] = pack2(h0.x, h0.y); hcp[1] = pack2(h0.z, h0.w);
            hcp[2] = pack2(h1.x, h1.y); hcp[3] = pack2(h1.z, h1.w);
            hpp[0] = pack2(vm.w, h0.x); hpp[1] = pack2(h0.y, h0.z);
            hpp[2] = pack2(h0.w, h1.x); hpp[3] = pack2(h1.y, h1.z);
        } else {
            #pragma unroll
            for (int jp = 0; jp < 4; jp++) {
                hcp[jp] = *(const u64*)(hr + 2*jp);
                hpp[jp] = *(const u64*)(hr - D + 2*jp);
            }
        }
        const ulonglong2* wc = wblk + c*64 + og;
        #pragma unroll
        for (int i = 0; i < 4; i++) {
            ulonglong2 wF = __ldg(wc + (i*2    )*8);   // (wf0,wf0),(wf1,wf1)
            ulonglong2 wG = __ldg(wc + (i*2 + 1)*8);   // (wg0,wg0),(wg1,wg1)
            #pragma unroll
            for (int jp = 0; jp < 4; jp++) {
                af[i][jp] = f2fma(wF.x, hpp[jp], af[i][jp]);
                af[i][jp] = f2fma(wF.y, hcp[jp], af[i][jp]);
                ag[i][jp] = f2fma(wG.x, hpp[jp], ag[i][jp]);
                ag[i][jp] = f2fma(wG.y, hcp[jp], ag[i][jp]);
            }
        }
    }
    #pragma unroll
    for (int i = 0; i < 4; i++) {
        float* op = sm + OFF_OUT + (og*4 + i)*STR + base;
        #pragma unroll
        for (int jp = 0; jp < 4; jp++) {
            float2 f = unp(af[i][jp]);
            float2 g = unp(ag[i][jp]);
            *(u64*)(op + 2*jp) = pack2(gact(f.x, g.x), gact(f.y, g.y));
        }
    }
}

// ---------------------------------------------------------------------------
// Phase B: s/r GEMM; skip accumulated in caller-held f32x2 pairs; h RMW in smem.
// ---------------------------------------------------------------------------
__device__ __forceinline__ void phaseB(float* sm, const ulonglong2* __restrict__ wblk,
                                       const float* __restrict__ bb, int og, int base,
                                       u64 sacc[4][4], bool edge)
{
    u64 as_[4][4], ar[4][4];
    #pragma unroll
    for (int i = 0; i < 4; i++) {
        u64 bsv = dup2(bb[64 + 2*(og*4 + i)]);
        u64 brv = dup2(bb[64 + 2*(og*4 + i) + 1]);
        #pragma unroll
        for (int jp = 0; jp < 4; jp++) { as_[i][jp] = bsv; ar[i][jp] = brv; }
    }
    const float* ob = sm + OFF_OUT + base;

    #pragma unroll 2
    for (int o = 0; o < 32; o++) {
        u64 op[4];
        #pragma unroll
        for (int jp = 0; jp < 4; jp++) op[jp] = *(const u64*)(ob + o*STR + 2*jp);
        const ulonglong2* wo = wblk + o*32 + og;
        ulonglong2 wS01 = __ldg(wo);
        ulonglong2 wS23 = __ldg(wo + 8);
        ulonglong2 wR01 = __ldg(wo + 16);
        ulonglong2 wR23 = __ldg(wo + 24);
        #pragma unroll
        for (int jp = 0; jp < 4; jp++) {
            as_[0][jp] = f2fma(wS01.x, op[jp], as_[0][jp]);
            as_[1][jp] = f2fma(wS01.y, op[jp], as_[1][jp]);
            as_[2][jp] = f2fma(wS23.x, op[jp], as_[2][jp]);
            as_[3][jp] = f2fma(wS23.y, op[jp], as_[3][jp]);
            ar[0][jp]  = f2fma(wR01.x, op[jp], ar[0][jp]);
            ar[1][jp]  = f2fma(wR01.y, op[jp], ar[1][jp]);
            ar[2][jp]  = f2fma(wR23.x, op[jp], ar[2][jp]);
            ar[3][jp]  = f2fma(wR23.y, op[jp], ar[3][jp]);
        }
    }
    #pragma unroll
    for (int i = 0; i < 4; i++) {
        u64* hp_ = (u64*)(sm + OFF_HS + (og*4 + i)*STR + base);
        #pragma unroll
        for (int jp = 0; jp < 4; jp++) {
            sacc[i][jp] = f2add(sacc[i][jp], as_[i][jp]);
            u64 r = ar[i][jp];
            if (edge) {
                float2 rv = unp(r);
                if (base + 2*jp     < HALO) rv.x = 0.f;
                if (base + 2*jp + 1 < HALO) rv.y = 0.f;
                r = pack2(rv.x, rv.y);
            }
            hp_[jp] = f2add(hp_[jp], r);
        }
    }
}

// ---------------------------------------------------------------------------
__global__ __launch_bounds__(NTHR, 1)
void k_wavenet(const float* __restrict__ x,
               const float* __restrict__ w0, const float* __restrict__ b0,
               const float* __restrict__ bf, const float* __restrict__ bg,
               const float* __restrict__ bs, const float* __restrict__ br,
               const float* __restrict__ wd, const float* __restrict__ bd)
{
    extern __shared__ float sm[];
    const int b = blockIdx.y, tile = blockIdx.x, t = threadIdx.x;
    const int l0 = tile * TT;

    // stage x (positions l0-65 .. l0+258) + zero left pad of hs
    for (int i = t; i < 324; i += NTHR) {
        int gp = l0 - 65 + i;
        sm[OFF_XS + i] = (gp >= 0 && gp < LLEN) ? x[(size_t)b*LLEN + gp] : 0.f;
    }
    if (t < 64) sm[t] = 0.f;
    __syncthreads();

    // initial causal conv K=3 -> hs[c][t]
    {
        float x0 = sm[OFF_XS + t], x1 = sm[OFF_XS + t + 1], x2 = sm[OFF_XS + t + 2];
        int p = l0 - HALO + t;
        bool v = (p >= 0 && p < LLEN);
        #pragma unroll
        for (int c = 0; c < CC; c++) {
            float h = v ? (__ldg(&b0[c]) + __ldg(&w0[3*c])*x0
                           + __ldg(&w0[3*c+1])*x1 + __ldg(&w0[3*c+2])*x2) : 0.f;
            sm[OFF_HS + c*STR + t] = h;
        }
    }
    // preload all biases: per block 128 floats: (bf,bg) pairs | (bs,br) pairs
    if (t < 192) {
        int blk = t >> 5, ch = t & 31;
        sm[OFF_B + blk*128 + 2*ch]      = bf[blk*CC + ch];
        sm[OFF_B + blk*128 + 2*ch + 1]  = bg[blk*CC + ch];
        sm[OFF_B + blk*128 + 64 + 2*ch] = bs[blk*CC + ch];
        sm[OFF_B + blk*128 + 65 + 2*ch] = br[blk*CC + ch];
    }
    __syncthreads();

    const int og = t & 7, base = (t >> 3) * 8;
    const bool edge = (l0 == 0) && (base < 64);
    u64 sacc[4][4];
    #pragma unroll
    for (int i = 0; i < 4; i++)
        #pragma unroll
        for (int jp = 0; jp < 4; jp++) sacc[i][jp] = 0ULL;

    const ulonglong2* wfgAll = (const ulonglong2*)g_wFG;
    const ulonglong2* wsrAll = (const ulonglong2*)g_wSR;

    #pragma unroll 1
    for (int blk = 0; blk < 6; blk++) {
        const ulonglong2* wa = wfgAll + blk*2048;
        const ulonglong2* wb = wsrAll + blk*1024;
        const float* bb = sm + OFF_B + blk*128;
        switch (blk) {
            case 0: phaseA<1>(sm, wa, bb, og, base);  break;
            case 1: phaseA<2>(sm, wa, bb, og, base);  break;
            case 2: phaseA<4>(sm, wa, bb, og, base);  break;
            case 3: phaseA<8>(sm, wa, bb, og, base);  break;
            case 4: phaseA<16>(sm, wa, bb, og, base); break;
            default: phaseA<32>(sm, wa, bb, og, base); break;
        }
        __syncthreads();
        phaseB(sm, wb, bb, og, base, sacc, edge);
        __syncthreads();
    }

    // dump skip pairs into the out buffer
    #pragma unroll
    for (int i = 0; i < 4; i++) {
        float* p_ = sm + OFF_OUT + (og*4 + i)*STR + base;
        #pragma unroll
        for (int jp = 0; jp < 4; jp++) *(u64*)(p_ + 2*jp) = sacc[i][jp];
    }
    __syncthreads();

    // repack skip into [c][m] float4 (taps 63+4m..63+4m+3) in hs region
    for (int idx = t; idx < 2048; idx += NTHR) {
        int c = idx >> 6, m = idx & 63;
        const float* sp = sm + OFF_OUT + c*STR + HALO + 4*m;
        ((float4*)(sm + OFF_HS))[idx] = make_float4(sp[0], sp[1], sp[2], sp[3]);
    }
    __syncthreads();

    // downsample conv: 64 out-ch, K=4, stride 4; wd via dedup'd LDG
    {
        int m = t & 63, oq0 = t >> 6;
        int mg = tile*64 + m;
        const float4* sdv = (const float4*)(sm + OFF_HS);
        const float4* wdv = (const float4*)wd;
        if (mg < DOWNL) {
            for (int oq = oq0; oq < 16; oq += 5) {
                int o0 = oq * 4;
                float a0 = 0.f, a1 = 0.f, a2 = 0.f, a3 = 0.f;
                #pragma unroll 4
                for (int c = 0; c < 32; c++) {
                    float4 sv = sdv[c*64 + m];
                    float4 w_;
                    w_ = __ldg(&wdv[(o0+0)*32 + c]); a0 += w_.x*sv.x + w_.y*sv.y + w_.z*sv.z + w_.w*sv.w;
                    w_ = __ldg(&wdv[(o0+1)*32 + c]); a1 += w_.x*sv.x + w_.y*sv.y + w_.z*sv.z + w_.w*sv.w;
                    w_ = __ldg(&wdv[(o0+2)*32 + c]); a2 += w_.x*sv.x + w_.y*sv.y + w_.z*sv.z + w_.w*sv.w;
                    w_ = __ldg(&wdv[(o0+3)*32 + c]); a3 += w_.x*sv.x + w_.y*sv.y + w_.z*sv.z + w_.w*sv.w;
                }
                size_t gb = (size_t)b*FLATN + (size_t)mg;
                g_y[gb + (size_t)(o0+0)*DOWNL] = a0 + __ldg(&bd[o0+0]);
                g_y[gb + (size_t)(o0+1)*DOWNL] = a1 + __ldg(&bd[o0+1]);
                g_y[gb + (size_t)(o0+2)*DOWNL] = a2 + __ldg(&bd[o0+2]);
                g_y[gb + (size_t)(o0+3)*DOWNL] = a3 + __ldg(&bd[o0+3]);
            }
        }
    }
}

// ---------------------------------------------------------------------------
// Kernel 2: FC partials
// ---------------------------------------------------------------------------
__global__ __launch_bounds__(256)
void k_fc(const float* __restrict__ fcW)
{
    extern __shared__ float ys[];
    const int t = threadIdx.x;
    const int slice = blockIdx.x;
    const size_t f0 = (size_t)slice * SLICE;

    for (int idx = t; idx < NB*(SLICE/4); idx += 256) {
        int bb = idx / (SLICE/4);
        int q  = idx % (SLICE/4);
        ((float4*)ys)[idx] = ((const float4*)(g_y + (size_t)bb*FLATN + f0))[q];
    }
    __syncthreads();

    const int warp = t >> 5, lane = t & 31;
    #pragma unroll 1
    for (int jp = 0; jp < 4; jp++) {
        int j0 = warp*8 + jp*2;
        const float4* w0p = (const float4*)(fcW + (size_t)j0*FLATN + f0);
        const float4* w1p = (const float4*)(fcW + (size_t)(j0+1)*FLATN + f0);
        float a0[NB], a1[NB];
        #pragma unroll
        for (int bb = 0; bb < NB; bb++) { a0[bb] = 0.f; a1[bb] = 0.f; }

        for (int q = lane; q < SLICE/4; q += 32) {
            float4 w0v = __ldg(w0p + q);
            float4 w1v = __ldg(w1p + q);
            #pragma unroll
            for (int bb = 0; bb < NB; bb++) {
                float4 yv = ((const float4*)ys)[bb*(SLICE/4) + q];
                a0[bb] += w0v.x*yv.x + w0v.y*yv.y + w0v.z*yv.z + w0v.w*yv.w;
                a1[bb] += w1v.x*yv.x + w1v.y*yv.y + w1v.z*yv.z + w1v.w*yv.w;
            }
        }
        #pragma unroll
        for (int bb = 0; bb < NB; bb++) {
            #pragma unroll
            for (int off = 16; off > 0; off >>= 1) {
                a0[bb] += __shfl_xor_sync(0xffffffffu, a0[bb], off);
                a1[bb] += __shfl_xor_sync(0xffffffffu, a1[bb], off);
            }
        }
        if (lane == 0) {
            #pragma unroll
            for (int bb = 0; bb < NB; bb++) {
                g_partial[((size_t)slice*64 + j0  )*NB + bb] = a0[bb];
                g_partial[((size_t)slice*64 + j0+1)*NB + bb] = a1[bb];
            }
        }
    }
}

// ---------------------------------------------------------------------------
// Kernel 3: final reduce + reparameterize
// ---------------------------------------------------------------------------
__global__ void k_final(const float* __restrict__ fcb,
                        const float* __restrict__ eps,
                        float* __restrict__ out)
{
    __shared__ float os[64][NB];
    const int t = threadIdx.x;   // 512
    const int j = t >> 3, bb = t & 7;
    float acc = fcb[j];
    for (int s = 0; s < NSLICE; s++)
        acc += g_partial[(size_t)s*64*NB + t];
    os[j][bb] = acc;
    __syncthreads();
    if (t < 256) {
        int b2 = t >> 5, c = t & 31;
        float mu = os[c][b2];
        float lv = os[c + 32][b2];
        float z  = mu + eps[b2*32 + c] * expf(0.5f * lv);
        out[        b2*32 + c] = mu;
        out[256  +  b2*32 + c] = lv;
        out[512  +  b2*32 + c] = z;
    }
}

// ---------------------------------------------------------------------------
extern "C" void kernel_launch(void* const* d_in, const int* in_sizes, int n_in,
                              void* d_out, int out_size)
{
    const float* x   = (const float*)d_in[0];
    const float* eps = (const float*)d_in[1];
    const float* w0  = (const float*)d_in[2];
    const float* b0  = (const float*)d_in[3];
    const float* Wf  = (const float*)d_in[4];
    const float* bf  = (const float*)d_in[5];
    const float* Wg  = (const float*)d_in[6];
    const float* bg  = (const float*)d_in[7];
    const float* Ws  = (const float*)d_in[8];
    const float* bs  = (const float*)d_in[9];
    const float* Wr  = (const float*)d_in[10];
    const float* br  = (const float*)d_in[11];
    const float* wd  = (const float*)d_in[12];
    const float* bd  = (const float*)d_in[13];
    const float* fcW = (const float*)d_in[14];
    const float* fcb = (const float*)d_in[15];
    float* out = (float*)d_out;

    const int smem1 = SMF * (int)sizeof(float);
    const int smem2 = NB * SLICE * (int)sizeof(float);
    cudaFuncSetAttribute(k_wavenet, cudaFuncAttributeMaxDynamicSharedMemorySize, smem1);
    cudaFuncSetAttribute(k_fc,      cudaFuncAttributeMaxDynamicSharedMemorySize, smem2);

    k_prep<<<48, 256>>>(Wf, Wg, Ws, Wr);
    dim3 g1(NTILES, NB);
    k_wavenet<<<g1, NTHR, smem1>>>(x, w0, b0, bf, bg, bs, br, wd, bd);
    k_fc<<<NSLICE, 256, smem2>>>(fcW);
    k_final<<<1, 512>>>(fcb, eps, out);
}